// round 9
// baseline (speedup 1.0000x reference)
#include <cuda_runtime.h>
#include <cuda_bf16.h>
#include <cstdint>

// ---------------------------------------------------------------------------
// GraphSAGE 2-layer backbone, CSR gather-reduce + zero-mov FFMA2 dense.
// R9: dense inner loop has NO operand-packing movs:
//   - weights __ldg'd as ulonglong2 (native 64-bit pairs)
//   - activations stored DUPLICATED (c,c) in smem, staged in 64-k phases
// ---------------------------------------------------------------------------

static constexpr int NN   = 100000;
static constexpr int EE   = 1600000;
static constexpr int F_IN = 64;
static constexpr int F_H  = 128;
static constexpr int SCAN_CHUNK = 512;
static constexpr int KH   = 64;          // k's per staging phase

__device__ __align__(16) float g_agg1 [(size_t)NN * F_IN];
__device__ __align__(16) float g_h    [(size_t)NN * F_H];
__device__ __align__(16) float g_agg2 [(size_t)NN * F_H];
__device__ __align__(16) float g_dinv [NN];
__device__ __align__(16) int   g_degi [NN];      // zero at load; final re-zeroes
__device__ __align__(16) int   g_rowp [NN + 1];
__device__ __align__(16) int   g_curs [NN];
__device__ __align__(16) int   g_csr  [EE];
__device__ __align__(16) int   g_bsum [256];
__device__ __align__(16) int   g_boff [256];
__device__ __align__(16) float g_w1t  [2 * F_IN * 128];
__device__ __align__(16) float g_w2t  [2 * F_H  * 128];

// ---------------------------------------------------------------------------
__device__ __forceinline__ unsigned long long pk2(float a, float b) {
    unsigned long long r;
    asm("mov.b64 %0, {%1, %2};" : "=l"(r) : "f"(a), "f"(b));
    return r;
}
__device__ __forceinline__ void fma2(unsigned long long& d,
                                     unsigned long long a,
                                     unsigned long long b) {
    asm("fma.rn.f32x2 %0, %1, %2, %0;" : "+l"(d) : "l"(a), "l"(b));
}
__device__ __forceinline__ float2 upk2(unsigned long long v) {
    float2 f;
    asm("mov.b64 {%0, %1}, %2;" : "=f"(f.x), "=f"(f.y) : "l"(v));
    return f;
}

// ---------------------------------------------------------------------------
__global__ void pack_all_kernel(const float* __restrict__ W1l,
                                const float* __restrict__ W1r,
                                const float* __restrict__ W2l,
                                const float* __restrict__ W2r,
                                float* __restrict__ w1t,
                                float* __restrict__ w2t) {
    int i = blockIdx.x * blockDim.x + threadIdx.x;
    if (i < 2 * F_IN * 128) {
        int k = i >> 7, j = i & 127;
        w1t[i] = (k < F_IN) ? W1l[j * F_IN + k] : W1r[j * F_IN + (k - F_IN)];
    }
    if (i < 2 * F_H * 128) {
        int k = i >> 7, j = i & 127;
        w2t[i] = (k < F_H) ? W2l[j * F_H + k] : W2r[j * F_H + (k - F_H)];
    }
}

__global__ void hist_kernel(const int* __restrict__ ei, int E, int nnodes,
                            int* __restrict__ degi) {
    int e = blockIdx.x * blockDim.x + threadIdx.x;
    if (e >= E) return;
    int dst = __ldg(&ei[E + e]);
    if ((unsigned)dst < (unsigned)nnodes) atomicAdd(&degi[dst], 1);
}

// ---- coalesced 3-pass exclusive scan over degi ----
__global__ void scan_partial_kernel(const int* __restrict__ degi,
                                    int* __restrict__ bsum, int n) {
    __shared__ int s[SCAN_CHUNK];
    int t = threadIdx.x;
    int i = blockIdx.x * SCAN_CHUNK + t;
    s[t] = (i < n) ? degi[i] : 0;
    __syncthreads();
    for (int off = SCAN_CHUNK / 2; off > 0; off >>= 1) {
        if (t < off) s[t] += s[t + off];
        __syncthreads();
    }
    if (t == 0) bsum[blockIdx.x] = s[0];
}

__global__ void scan_bsum_kernel(const int* __restrict__ bsum,
                                 int* __restrict__ boff,
                                 int* __restrict__ rowp,
                                 int nblk, int n) {
    __shared__ int s[256];
    int t = threadIdx.x;
    s[t] = (t < nblk) ? bsum[t] : 0;
    __syncthreads();
    for (int off = 1; off < 256; off <<= 1) {
        int v = (t >= off) ? s[t - off] : 0;
        __syncthreads();
        s[t] += v;
        __syncthreads();
    }
    boff[t] = (t == 0) ? 0 : s[t - 1];
    if (t == 255) rowp[n] = s[255];
}

__global__ void scan_final_kernel(int* __restrict__ degi,
                                  const int* __restrict__ boff,
                                  int* __restrict__ rowp,
                                  int* __restrict__ curs,
                                  float* __restrict__ dinv, int n) {
    __shared__ int s[SCAN_CHUNK];
    int t = threadIdx.x;
    int i = blockIdx.x * SCAN_CHUNK + t;
    int d = (i < n) ? degi[i] : 0;
    s[t] = d;
    __syncthreads();
    for (int off = 1; off < SCAN_CHUNK; off <<= 1) {
        int v = (t >= off) ? s[t - off] : 0;
        __syncthreads();
        s[t] += v;
        __syncthreads();
    }
    if (i < n) {
        int excl = s[t] - d + boff[blockIdx.x];
        rowp[i] = excl;
        curs[i] = excl;
        dinv[i] = 1.0f / fmaxf((float)d, 1.0f);
        degi[i] = 0;
    }
}

__global__ void scatter_kernel(const int* __restrict__ ei, int E, int nnodes,
                               int* __restrict__ curs,
                               int* __restrict__ csr) {
    int e = blockIdx.x * blockDim.x + threadIdx.x;
    if (e >= E) return;
    int src = __ldg(&ei[e]);
    int dst = __ldg(&ei[E + e]);
    if ((unsigned)src >= (unsigned)nnodes || (unsigned)dst >= (unsigned)nnodes) return;
    int pos = atomicAdd(&curs[dst], 1);
    csr[pos] = src;
}

// Gather-reduce mean aggregation, 4-way unroll.
template <int F4>
__global__ void gather_agg_kernel(const float4* __restrict__ in4,
                                  const int* __restrict__ rowp,
                                  const int* __restrict__ csr,
                                  const float* __restrict__ dinv,
                                  float4* __restrict__ aggout,
                                  int n) {
    constexpr int GPB = 256 / F4;
    const int node = blockIdx.x * GPB + (threadIdx.x / F4);
    const int lane = threadIdx.x & (F4 - 1);
    if (node >= n) return;

    const int beg = __ldg(&rowp[node]);
    const int end = __ldg(&rowp[node + 1]);

    float4 a0 = make_float4(0.f, 0.f, 0.f, 0.f);
    float4 a1 = make_float4(0.f, 0.f, 0.f, 0.f);
    float4 a2 = make_float4(0.f, 0.f, 0.f, 0.f);
    float4 a3 = make_float4(0.f, 0.f, 0.f, 0.f);

    int j = beg;
    for (; j + 4 <= end; j += 4) {
        int s0 = __ldg(&csr[j]);
        int s1 = __ldg(&csr[j + 1]);
        int s2 = __ldg(&csr[j + 2]);
        int s3 = __ldg(&csr[j + 3]);
        float4 v0 = __ldg(&in4[(size_t)s0 * F4 + lane]);
        float4 v1 = __ldg(&in4[(size_t)s1 * F4 + lane]);
        float4 v2 = __ldg(&in4[(size_t)s2 * F4 + lane]);
        float4 v3 = __ldg(&in4[(size_t)s3 * F4 + lane]);
        a0.x += v0.x; a0.y += v0.y; a0.z += v0.z; a0.w += v0.w;
        a1.x += v1.x; a1.y += v1.y; a1.z += v1.z; a1.w += v1.w;
        a2.x += v2.x; a2.y += v2.y; a2.z += v2.z; a2.w += v2.w;
        a3.x += v3.x; a3.y += v3.y; a3.z += v3.z; a3.w += v3.w;
    }
    for (; j < end; j++) {
        int s0 = __ldg(&csr[j]);
        float4 v0 = __ldg(&in4[(size_t)s0 * F4 + lane]);
        a0.x += v0.x; a0.y += v0.y; a0.z += v0.z; a0.w += v0.w;
    }

    const float di = __ldg(&dinv[node]);
    float4 r;
    r.x = (a0.x + a1.x + a2.x + a3.x) * di;
    r.y = (a0.y + a1.y + a2.y + a3.y) * di;
    r.z = (a0.z + a1.z + a2.z + a3.z) * di;
    r.w = (a0.w + a1.w + a2.w + a3.w) * di;
    aggout[(size_t)node * F4 + lane] = r;
}

// Fused dense layer, zero-mov FFMA2 inner loop.
// Tile: 64 nodes. Smem holds one 64-k phase of the concat activation,
// DUPLICATED (c,c) so LDS.128 yields two (c,c) register pairs.
// Weights __ldg'd as ulonglong2 (native pairs). NPH = 2K/64 phases.
template <int K, bool RELU>
__global__ void __launch_bounds__(256)
dense_kernel(const float* __restrict__ xin,
             const float* __restrict__ agg,
             const float* __restrict__ WcT,
             const float* __restrict__ bias,
             float* __restrict__ out,
             int nnodes) {
    constexpr int K2  = 2 * K;
    constexpr int NPH = K2 / KH;                  // phases of 64 k
    extern __shared__ float sm[];                 // sD: 64 nodes * KH * 2 floats (32KB)
    float* sD = sm;
    __shared__ float sB[128];

    const int tid  = threadIdx.x;
    const int base = blockIdx.x * 64;
    const int w    = tid >> 5;
    const int l    = tid & 31;

    if (tid < 128) sB[tid] = bias[tid];
    __syncthreads();   // sB ready before acc init

    unsigned long long acc01[8], acc23[8];
    {
        unsigned long long b01 = pk2(sB[4 * l], sB[4 * l + 1]);
        unsigned long long b23 = pk2(sB[4 * l + 2], sB[4 * l + 3]);
#pragma unroll
        for (int m = 0; m < 8; m++) { acc01[m] = b01; acc23[m] = b23; }
    }

    const ulonglong2* W16 = reinterpret_cast<const ulonglong2*>(WcT);

#pragma unroll
    for (int ph = 0; ph < NPH; ph++) {
        // ---- stage phase ph: 64 k's of concat(agg, x), duplicated ----
        {
            const float* src = (ph < NPH / 2) ? (agg + ph * KH)
                                              : (xin + (ph - NPH / 2) * KH);
            const float4* s4 = reinterpret_cast<const float4*>(src);
            float4 z = make_float4(0.f, 0.f, 0.f, 0.f);
            // 64 nodes * 16 float4-chunks
            for (int i = tid; i < 64 * 16; i += 256) {
                int nn = i >> 4;
                int kq = i & 15;
                int node = base + nn;
                float4 v = z;
                if (node < nnodes) v = s4[(size_t)node * (K / 4) + kq];
                float* d = sD + (nn * KH + kq * 4) * 2;
                reinterpret_cast<float4*>(d)[0] = make_float4(v.x, v.x, v.y, v.y);
                reinterpret_cast<float4*>(d)[1] = make_float4(v.z, v.z, v.w, v.w);
            }
        }
        __syncthreads();

        const ulonglong2* sDw = reinterpret_cast<const ulonglong2*>(
            sD + (w * 8) * KH * 2);

#pragma unroll 4
        for (int k4 = 0; k4 < KH / 4; k4++) {
            const int gk = ph * KH + 4 * k4;
            ulonglong2 w0 = __ldg(&W16[(gk + 0) * 32 + l]);   // (wj0,wj1),(wj2,wj3)
            ulonglong2 w1 = __ldg(&W16[(gk + 1) * 32 + l]);
            ulonglong2 w2 = __ldg(&W16[(gk + 2) * 32 + l]);
            ulonglong2 w3 = __ldg(&W16[(gk + 3) * 32 + l]);
#pragma unroll
            for (int m = 0; m < 8; m++) {
                // (ck,ck,ck+1,ck+1) and (ck+2,ck+2,ck+3,ck+3), broadcast LDS.128
                ulonglong2 c01 = sDw[m * (KH / 2) + k4 * 2];
                ulonglong2 c23 = sDw[m * (KH / 2) + k4 * 2 + 1];
                fma2(acc01[m], c01.x, w0.x); fma2(acc23[m], c01.x, w0.y);
                fma2(acc01[m], c01.y, w1.x); fma2(acc23[m], c01.y, w1.y);
                fma2(acc01[m], c23.x, w2.x); fma2(acc23[m], c23.x, w2.y);
                fma2(acc01[m], c23.y, w3.x); fma2(acc23[m], c23.y, w3.y);
            }
        }
        __syncthreads();   // all warps done with phase before re-stage
    }

#pragma unroll
    for (int m = 0; m < 8; m++) {
        int node = base + w * 8 + m;
        if (node >= nnodes) continue;
        float2 p01 = upk2(acc01[m]);
        float2 p23 = upk2(acc23[m]);
        float4 o;
        o.x = p01.x; o.y = p01.y; o.z = p23.x; o.w = p23.y;
        if (RELU) {
            o.x = fmaxf(o.x, 0.f); o.y = fmaxf(o.y, 0.f);
            o.z = fmaxf(o.z, 0.f); o.w = fmaxf(o.w, 0.f);
        }
        reinterpret_cast<float4*>(out)[(size_t)node * 32 + l] = o;
    }
}

// ---------------------------------------------------------------------------
extern "C" void kernel_launch(void* const* d_in, const int* in_sizes, int n_in,
                              void* d_out, int out_size) {
    const float* x    = (const float*)d_in[0];
    const int*   ei   = (const int*)d_in[1];
    const float* W1_l = (const float*)d_in[2];
    const float* b1   = (const float*)d_in[3];
    const float* W1_r = (const float*)d_in[4];
    const float* W2_l = (const float*)d_in[5];
    const float* b2   = (const float*)d_in[6];
    const float* W2_r = (const float*)d_in[7];
    float*       out  = (float*)d_out;

    const int n = in_sizes[0] / F_IN;   // 100000
    const int E = in_sizes[1] / 2;      // 1600000
    const int nblk = (n + SCAN_CHUNK - 1) / SCAN_CHUNK;

    void *p_agg1, *p_h, *p_agg2, *p_dinv, *p_degi, *p_rowp, *p_curs, *p_csr,
         *p_bsum, *p_boff, *p_w1t, *p_w2t;
    cudaGetSymbolAddress(&p_agg1, g_agg1);
    cudaGetSymbolAddress(&p_h,    g_h);
    cudaGetSymbolAddress(&p_agg2, g_agg2);
    cudaGetSymbolAddress(&p_dinv, g_dinv);
    cudaGetSymbolAddress(&p_degi, g_degi);
    cudaGetSymbolAddress(&p_rowp, g_rowp);
    cudaGetSymbolAddress(&p_curs, g_curs);
    cudaGetSymbolAddress(&p_csr,  g_csr);
    cudaGetSymbolAddress(&p_bsum, g_bsum);
    cudaGetSymbolAddress(&p_boff, g_boff);
    cudaGetSymbolAddress(&p_w1t,  g_w1t);
    cudaGetSymbolAddress(&p_w2t,  g_w2t);
    float* agg1 = (float*)p_agg1;
    float* h    = (float*)p_h;
    float* agg2 = (float*)p_agg2;
    float* dinv = (float*)p_dinv;
    int*   degi = (int*)p_degi;
    int*   rowp = (int*)p_rowp;
    int*   curs = (int*)p_curs;
    int*   csr  = (int*)p_csr;
    int*   bsum = (int*)p_bsum;
    int*   boff = (int*)p_boff;
    float* w1t  = (float*)p_w1t;
    float* w2t  = (float*)p_w2t;

    const int smemD = 64 * KH * 2 * (int)sizeof(float);   // 32KB both layers
    cudaFuncSetAttribute(dense_kernel<F_IN, true>,
                         cudaFuncAttributeMaxDynamicSharedMemorySize, smemD);
    cudaFuncSetAttribute(dense_kernel<F_H, false>,
                         cudaFuncAttributeMaxDynamicSharedMemorySize, smemD);

    // CSR build (degi zero: zero-init at load, re-zeroed by scan_final)
    hist_kernel<<<(E + 255) / 256, 256>>>(ei, E, n, degi);
    scan_partial_kernel<<<nblk, SCAN_CHUNK>>>(degi, bsum, n);
    scan_bsum_kernel<<<1, 256>>>(bsum, boff, rowp, nblk, n);
    scan_final_kernel<<<nblk, SCAN_CHUNK>>>(degi, boff, rowp, curs, dinv, n);
    scatter_kernel<<<(E + 255) / 256, 256>>>(ei, E, n, curs, csr);

    // layer 1
    gather_agg_kernel<F_IN / 4><<<(n * (F_IN / 4) + 255) / 256, 256>>>(
        (const float4*)x, rowp, csr, dinv, (float4*)agg1, n);
    pack_all_kernel<<<(2 * F_H * 128 + 255) / 256, 256>>>(
        W1_l, W1_r, W2_l, W2_r, w1t, w2t);
    dense_kernel<F_IN, true><<<(n + 63) / 64, 256, smemD>>>(
        x, agg1, w1t, b1, h, n);

    // layer 2
    gather_agg_kernel<F_H / 4><<<(n * (F_H / 4) + 255) / 256, 256>>>(
        (const float4*)h, rowp, csr, dinv, (float4*)agg2, n);
    dense_kernel<F_H, false><<<(n + 63) / 64, 256, smemD>>>(
        h, agg2, w2t, b2, out, n);
}